// round 9
// baseline (speedup 1.0000x reference)
#include <cuda_runtime.h>
#include <math.h>

// SLAYFeatures overlapped producer/expander, single kernel.
//  Producer blocks (0..2047):  NB=4 rows -> poly (g_poly) + weighted prf (g_prf),
//                              then release flag.
//  Expander blocks (2048..10239): 1 row each; spin on flag, stage 5KB in smem,
//                              stream 16KB of coalesced __stcs stores.
// Flags self-reset (4 consumers per flag) -> deterministic across graph replays.

#define NBP 4
#define THREADS 256
#define NPROD 2048          // 8192 / NBP

__device__ float g_poly[8192 * 256];     // 8 MB  [b][h*16+p]
__device__ float g_prf [8192 * 1024];    // 32 MB [b][r*512 + h*32 + m]
__device__ int   g_flag[NPROD];          // zero-init; reset each pass
__device__ int   g_done[NPROD];          // consumer count per flag

__global__ __launch_bounds__(THREADS, 4) void slay_overlap(
    const float* __restrict__ x,        // [8192,1024]
    const float* __restrict__ omega,    // [2,16,64,32]
    const float* __restrict__ anchors,  // [16,64]
    float* __restrict__ out,            // [8192,16384]
    float s0, float s1, float c0, float c1, float e0, float e1)
{
    const int t = threadIdx.x;

    if (blockIdx.x < NPROD) {
        // ================= PRODUCER =================
        __shared__ __align__(16) float xs[NBP][1024];   // 16 KB
        const int blk = blockIdx.x;
        const int b0  = blk * NBP;

        // Phase 1: load + per-head normalize (16 consecutive lanes share a head)
        {
            float4 v[NBP];
            float  ss[NBP];
            const float4* x4 = (const float4*)x;
#pragma unroll
            for (int k = 0; k < NBP; k++) {
                v[k] = x4[(size_t)(b0 + k) * 256 + t];
                ss[k] = v[k].x*v[k].x + v[k].y*v[k].y + v[k].z*v[k].z + v[k].w*v[k].w;
            }
#pragma unroll
            for (int k = 0; k < NBP; k++) {
#pragma unroll
                for (int off = 8; off; off >>= 1)
                    ss[k] += __shfl_xor_sync(0xffffffffu, ss[k], off);
                float inv = 1.0f / (sqrtf(fmaxf(ss[k], 1e-12f)) + 1e-4f);
                float4 w = v[k];
                w.x *= inv; w.y *= inv; w.z *= inv; w.w *= inv;
                ((float4*)xs[k])[t] = w;
            }
        }
        __syncthreads();

        // Phase 2: poly -> g_poly. thread = (h, p)
        {
            const int h = t >> 4, p = t & 15;
            float acc[NBP];
#pragma unroll
            for (int k = 0; k < NBP; k++) acc[k] = 0.0f;
            const float4* an = (const float4*)(anchors + p * 64);
#pragma unroll 4
            for (int d4 = 0; d4 < 16; d4++) {
                float4 a = an[d4];
#pragma unroll
                for (int k = 0; k < NBP; k++) {
                    float4 xv = ((const float4*)xs[k])[h * 16 + d4];
                    acc[k] += xv.x*a.x + xv.y*a.y + xv.z*a.z + xv.w*a.w;
                }
            }
#pragma unroll
            for (int k = 0; k < NBP; k++)
                g_poly[(size_t)(b0 + k) * 256 + t] = acc[k] * acc[k] * 0.25f;
        }

        // Phase 3: prf -> g_prf. thread = (r, h, m4), omega amortized over 4 rows
        {
            const int r  = t >> 7;
            const int h  = (t >> 3) & 15;
            const int m4 = t & 7;

            float4 acc[NBP];
#pragma unroll
            for (int k = 0; k < NBP; k++) acc[k] = make_float4(0.f, 0.f, 0.f, 0.f);

            const float4* og = (const float4*)omega + (size_t)((r * 16 + h) * 64) * 8 + m4;
#pragma unroll 4
            for (int d4 = 0; d4 < 16; d4++) {
                float4 o0 = og[(4 * d4 + 0) * 8];
                float4 o1 = og[(4 * d4 + 1) * 8];
                float4 o2 = og[(4 * d4 + 2) * 8];
                float4 o3 = og[(4 * d4 + 3) * 8];
#pragma unroll
                for (int k = 0; k < NBP; k++) {
                    float4 xv = ((const float4*)xs[k])[h * 16 + d4];
                    acc[k].x += xv.x*o0.x; acc[k].y += xv.x*o0.y; acc[k].z += xv.x*o0.z; acc[k].w += xv.x*o0.w;
                    acc[k].x += xv.y*o1.x; acc[k].y += xv.y*o1.y; acc[k].z += xv.y*o1.z; acc[k].w += xv.y*o1.w;
                    acc[k].x += xv.z*o2.x; acc[k].y += xv.z*o2.y; acc[k].z += xv.z*o2.z; acc[k].w += xv.z*o2.w;
                    acc[k].x += xv.w*o3.x; acc[k].y += xv.w*o3.y; acc[k].z += xv.w*o3.z; acc[k].w += xv.w*o3.w;
                }
            }

            const float sr = r ? s1 : s0;
            const float cr = r ? c1 : c0;
            const float er = r ? e1 : e0;

#pragma unroll
            for (int k = 0; k < NBP; k++) {
                float4 a = acc[k];
                float4 pr;
                pr.x = er * __expf(fminf(fmaxf(a.x * cr - sr, -20.f), 20.f));
                pr.y = er * __expf(fminf(fmaxf(a.y * cr - sr, -20.f), 20.f));
                pr.z = er * __expf(fminf(fmaxf(a.z * cr - sr, -20.f), 20.f));
                pr.w = er * __expf(fminf(fmaxf(a.w * cr - sr, -20.f), 20.f));
                *(float4*)&g_prf[(size_t)(b0 + k) * 1024 + r * 512 + h * 32 + m4 * 4] = pr;
            }
        }

        // Release: make scratch visible, then set flag.
        __threadfence();
        __syncthreads();
        if (t == 0) atomicExch(&g_flag[blk], 1);
    } else {
        // ================= EXPANDER =================
        __shared__ __align__(16) float pl[256];
        __shared__ __align__(16) float pf[1024];

        const int b = blockIdx.x - NPROD;     // row 0..8191
        const int f = b >> 2;                 // flag index (NBP=4 rows per flag)

        if (t == 0) {
            while (atomicAdd(&g_flag[f], 0) == 0) __nanosleep(64);
            __threadfence();                  // acquire
        }
        __syncthreads();

        pl[t] = g_poly[(size_t)b * 256 + t];
        ((float4*)pf)[t] = ((const float4*)(g_prf + (size_t)b * 1024))[t];
        __syncthreads();

        float4* ob = (float4*)(out + (size_t)b * 16384);
#pragma unroll
        for (int i = 0; i < 16; i++) {
            const int fi = i * 256 + t;       // float4 index: r*2048 + h*128 + p*8 + m4
            const int m4 = fi & 7;
            const int p  = (fi >> 3) & 15;
            const int h  = (fi >> 7) & 15;
            const int r  = fi >> 11;
            const float s = pl[h * 16 + p];
            float4 v = ((const float4*)pf)[r * 128 + h * 8 + m4];
            v.x *= s; v.y *= s; v.z *= s; v.w *= s;
            __stcs(&ob[fi], v);
        }

        // Self-reset for next graph replay: 4th consumer zeroes flag + counter.
        __syncthreads();
        if (t == 0) {
            int prev = atomicAdd(&g_done[f], 1);
            if (prev == 3) {
                g_done[f] = 0;
                atomicExch(&g_flag[f], 0);
            }
        }
    }
}

extern "C" void kernel_launch(void* const* d_in, const int* in_sizes, int n_in,
                              void* d_out, int out_size) {
    const float* x       = (const float*)d_in[0];
    const float* omega   = (const float*)d_in[1];
    const float* anchors = (const float*)d_in[2];
    float* out = (float*)d_out;

    const double C   = 2.0 + 1e-6;
    const double rt2 = 1.4142135623730951;
    const double n0d = 2.0 - rt2, n1d = 2.0 + rt2;
    const double w0d = (2.0 + rt2) / 4.0, w1d = (2.0 - rt2) / 4.0;

    float s0 = (float)(n0d / C);
    float s1 = (float)(n1d / C);
    float c0 = sqrtf(2.0f * s0);
    float c1 = sqrtf(2.0f * s1);
    float invSqrtM = 1.0f / sqrtf(32.0f);
    float e0 = sqrtf((float)(w0d / C)) * invSqrtM;
    float e1 = sqrtf((float)(w1d / C)) * invSqrtM;

    slay_overlap<<<NPROD + 8192, THREADS>>>(x, omega, anchors, out,
                                            s0, s1, c0, c1, e0, e1);
    (void)in_sizes; (void)n_in; (void)out_size;
}